// round 1
// baseline (speedup 1.0000x reference)
#include <cuda_runtime.h>
#include <math.h>
#include <stdint.h>

#define NBATCH 2
#define CHN 64
#define NY 80
#define NX 80
#define NCLS 80
#define KTOT (NCLS*NY*NX)   /* 512000 */
#define NO 85
#define OC3 192             /* 64 hm + 64 wh + 64 reg intermediate channels */
#define NU 84               /* stage2 outputs: 80 hm + 2 wh + 2 reg */

/* ---------------- device scratch (static, no allocations) ---------------- */
__device__ float g_w1t[64 * OC3 * 9];     /* [ci][oc(192)][9] transposed 3x3 weights */
__device__ float g_w2[NU * 64];           /* merged 1x1 weights [u][ci] */
__device__ float g_b1[OC3];
__device__ float g_b2[NU];
__device__ float g_hm[NBATCH * KTOT];     /* sigmoid heatmap, [b][c][y][x] = scan order */
__device__ float g_xywh[NBATCH * NY * NX * 4];
__device__ unsigned char g_flags[NBATCH * KTOT];
__device__ int g_bcount[1000];
__device__ int g_boff[1000];

/* ---------------- weight prep ---------------- */
__global__ void prep_w1(const float* __restrict__ hm, const float* __restrict__ wh,
                        const float* __restrict__ rg) {
    int idx = blockIdx.x * 256 + threadIdx.x;
    if (idx >= 64 * OC3 * 9) return;
    int ci = idx / (OC3 * 9);
    int r  = idx - ci * (OC3 * 9);
    int oc = r / 9;
    int k  = r - oc * 9;
    const float* src = (oc < 64) ? hm : (oc < 128) ? wh : rg;
    int o = oc & 63;
    g_w1t[idx] = src[o * 576 + ci * 9 + k];
}

__global__ void prep_rest(const float* __restrict__ hm_b1, const float* __restrict__ wh_b1,
                          const float* __restrict__ reg_b1,
                          const float* __restrict__ hm_w2, const float* __restrict__ wh_w2,
                          const float* __restrict__ reg_w2,
                          const float* __restrict__ hm_b2, const float* __restrict__ wh_b2,
                          const float* __restrict__ reg_b2) {
    int t = blockIdx.x * 256 + threadIdx.x;
    if (t < OC3) g_b1[t] = (t < 64) ? hm_b1[t] : (t < 128) ? wh_b1[t - 64] : reg_b1[t - 128];
    if (t < NU)  g_b2[t] = (t < 80) ? hm_b2[t] : (t < 82) ? wh_b2[t - 80] : reg_b2[t - 82];
    if (t < NU * 64) {
        int u = t >> 6, ci = t & 63;
        g_w2[t] = (u < 80) ? hm_w2[u * 64 + ci]
                : (u < 82) ? wh_w2[(u - 80) * 64 + ci]
                           : reg_w2[(u - 82) * 64 + ci];
    }
}

/* ---------------- fused conv kernel ----------------
   Tile: 8x4 pixels per block, 256 threads, all 192 3x3-conv channels,
   then fused 1x1 heads + sigmoid + bbox decode.                       */
#define TTX 8
#define TTY 4
#define S_IN_SZ (64 * 6 * 10)
#define S_W_SZ  (2 * OC3 * 9)
#define S_U_STR 193
#define S_U_SZ  (32 * S_U_STR)
#define S_W2_STR 65
#define S_W2_SZ (NU * S_W2_STR)
#define SMEM_FLOATS (S_IN_SZ + S_W_SZ + S_U_SZ + S_W2_SZ + OC3 + NU)
#define SMEM_BYTES  (SMEM_FLOATS * 4)

__global__ __launch_bounds__(256, 2) void conv_kernel(const float* __restrict__ x,
                                                      const float* __restrict__ offsets) {
    extern __shared__ float sm[];
    float* s_in = sm;                    /* [64][6][10] input tile + halo */
    float* s_w  = s_in + S_IN_SZ;        /* double-buffered [192][9] per-ci slab */
    float* s_u  = s_w + S_W_SZ;          /* [32 px][192] relu intermediates, stride 193 */
    float* s_w2 = s_u + S_U_SZ;          /* [84][64] 1x1 weights, stride 65 */
    float* s_b1 = s_w2 + S_W2_SZ;
    float* s_b2 = s_b1 + OC3;

    int tid = threadIdx.x;
    int bid = blockIdx.x;
    int b = bid / 200;
    int t = bid - b * 200;
    int y0 = (t / 10) * TTY;
    int x0 = (t % 10) * TTX;

    for (int i = tid; i < OC3; i += 256) s_b1[i] = g_b1[i];
    for (int i = tid; i < NU; i += 256)  s_b2[i] = g_b2[i];
    for (int i = tid; i < NU * 64; i += 256) {
        int u = i >> 6, ci = i & 63;
        s_w2[u * S_W2_STR + ci] = g_w2[i];
    }

    const float* xb = x + (size_t)b * CHN * NY * NX;
    for (int i = tid; i < S_IN_SZ; i += 256) {
        int ci = i / 60;
        int r  = (i % 60) / 10;
        int c  = i % 10;
        int gy = y0 + r - 1, gx = x0 + c - 1;
        float v = 0.f;
        if ((unsigned)gy < NY && (unsigned)gx < NX) v = xb[(ci * NY + gy) * NX + gx];
        s_in[i] = v;
    }
    for (int i = tid; i < OC3 * 9; i += 256) s_w[i] = g_w1t[i];
    __syncthreads();

    int pxg = tid & 7;        /* 8 pixel groups: 4 rows x 2 col-quads */
    int ocg = tid >> 3;       /* 32 oc groups of 6 */
    int row = pxg >> 1;
    int c0  = (pxg & 1) * 4;

    float acc[6][4];
#pragma unroll
    for (int o = 0; o < 6; o++)
#pragma unroll
        for (int p = 0; p < 4; p++) acc[o][p] = 0.f;

    float pf[7];
    for (int ci = 0; ci < 64; ci++) {
        int buf = ci & 1;
        if (ci + 1 < 64) {
            const float* src = g_w1t + (ci + 1) * (OC3 * 9);
#pragma unroll
            for (int j = 0; j < 7; j++) {
                int idx = tid + j * 256;
                pf[j] = (idx < OC3 * 9) ? src[idx] : 0.f;
            }
        }
        const float* sinb = s_in + ci * 60 + row * 10 + c0;
        float a[3][6];
#pragma unroll
        for (int rr = 0; rr < 3; rr++)
#pragma unroll
            for (int cc = 0; cc < 6; cc++) a[rr][cc] = sinb[rr * 10 + cc];

        const float* wp = s_w + buf * (OC3 * 9) + ocg * 54;
#pragma unroll
        for (int o = 0; o < 6; o++) {
            float w0 = wp[o * 9 + 0], w1 = wp[o * 9 + 1], w2 = wp[o * 9 + 2];
            float w3 = wp[o * 9 + 3], w4 = wp[o * 9 + 4], w5 = wp[o * 9 + 5];
            float w6 = wp[o * 9 + 6], w7 = wp[o * 9 + 7], w8 = wp[o * 9 + 8];
#pragma unroll
            for (int p = 0; p < 4; p++) {
                float s = acc[o][p];
                s += a[0][p] * w0; s += a[0][p + 1] * w1; s += a[0][p + 2] * w2;
                s += a[1][p] * w3; s += a[1][p + 1] * w4; s += a[1][p + 2] * w5;
                s += a[2][p] * w6; s += a[2][p + 1] * w7; s += a[2][p + 2] * w8;
                acc[o][p] = s;
            }
        }
        if (ci + 1 < 64) {
            float* dst = s_w + (buf ^ 1) * (OC3 * 9);
#pragma unroll
            for (int j = 0; j < 7; j++) {
                int idx = tid + j * 256;
                if (idx < OC3 * 9) dst[idx] = pf[j];
            }
        }
        __syncthreads();
    }

    /* stash relu(conv3x3 + b1) intermediates */
#pragma unroll
    for (int o = 0; o < 6; o++) {
        int oc = ocg * 6 + o;
        float bia = s_b1[oc];
#pragma unroll
        for (int p = 0; p < 4; p++) {
            int px = row * TTX + c0 + p;
            s_u[px * S_U_STR + oc] = fmaxf(acc[o][p] + bia, 0.f);
        }
    }
    __syncthreads();

    /* stage 2: 1x1 convs + sigmoid / bbox decode. 21 groups of 4 outputs x 8 px-quads */
    if (tid < 168) {
        int pxq = tid & 7;
        int g   = tid >> 3;   /* 0..20 */
        float acc2[4][4];
#pragma unroll
        for (int s = 0; s < 4; s++)
#pragma unroll
            for (int p = 0; p < 4; p++) acc2[s][p] = 0.f;

        if (g < 20) {
            const float* w0 = s_w2 + (g * 4 + 0) * S_W2_STR;
            const float* w1 = s_w2 + (g * 4 + 1) * S_W2_STR;
            const float* w2 = s_w2 + (g * 4 + 2) * S_W2_STR;
            const float* w3 = s_w2 + (g * 4 + 3) * S_W2_STR;
#pragma unroll 4
            for (int ci = 0; ci < 64; ci++) {
                float v0 = w0[ci], v1 = w1[ci], v2 = w2[ci], v3 = w3[ci];
#pragma unroll
                for (int p = 0; p < 4; p++) {
                    float uv = s_u[(pxq * 4 + p) * S_U_STR + ci];
                    acc2[0][p] += uv * v0;
                    acc2[1][p] += uv * v1;
                    acc2[2][p] += uv * v2;
                    acc2[3][p] += uv * v3;
                }
            }
#pragma unroll
            for (int s = 0; s < 4; s++) {
                int u = g * 4 + s;
                float bia = s_b2[u];
#pragma unroll
                for (int p = 0; p < 4; p++) {
                    float v = acc2[s][p] + bia;
                    float sig = 1.f / (1.f + expf(-v));
                    int px = pxq * 4 + p;
                    int gy = y0 + (px >> 3), gx = x0 + (px & 7);
                    g_hm[b * KTOT + u * (NY * NX) + gy * NX + gx] = sig;
                }
            }
        } else {
            /* g==20: wh_x, wh_y, reg_x, reg_y */
            const float* w0 = s_w2 + 80 * S_W2_STR;
            const float* w1 = s_w2 + 81 * S_W2_STR;
            const float* w2 = s_w2 + 82 * S_W2_STR;
            const float* w3 = s_w2 + 83 * S_W2_STR;
#pragma unroll 4
            for (int ci = 0; ci < 64; ci++) {
                float v0 = w0[ci], v1 = w1[ci], v2 = w2[ci], v3 = w3[ci];
#pragma unroll
                for (int p = 0; p < 4; p++) {
                    float uw = s_u[(pxq * 4 + p) * S_U_STR + 64 + ci];
                    float ur = s_u[(pxq * 4 + p) * S_U_STR + 128 + ci];
                    acc2[0][p] += uw * v0;
                    acc2[1][p] += uw * v1;
                    acc2[2][p] += ur * v2;
                    acc2[3][p] += ur * v3;
                }
            }
            float offx = offsets[b * 3 + 1] * 2.f;
            float offy = offsets[b * 3 + 2] * 2.f;
#pragma unroll
            for (int p = 0; p < 4; p++) {
                int px = pxq * 4 + p;
                int gy = y0 + (px >> 3), gx = x0 + (px & 7);
                float whx = fmaxf(acc2[0][p] + s_b2[80], 0.f);
                float why = fmaxf(acc2[1][p] + s_b2[81], 0.f);
                float rgx = fmaxf(acc2[2][p] + s_b2[82], 0.f);
                float rgy = fmaxf(acc2[3][p] + s_b2[83], 0.f);
                float cx = ((float)gx + offx + rgx) * 4.f;
                float cy = ((float)gy + offy + rgy) * 4.f;
                float* q = g_xywh + ((size_t)b * (NY * NX) + gy * NX + gx) * 4;
                q[0] = cx; q[1] = cy; q[2] = whx * 4.f; q[3] = why * 4.f;
            }
        }
    }
}

/* ---------------- maxima mask + per-block counts ---------------- */
__global__ void mask_kernel() {
    int bid = blockIdx.x;
    int b = bid / 500;
    int i = (bid - b * 500) * 1024 + threadIdx.x;
    const float* hmp = g_hm + (size_t)b * KTOT;
    float c = hmp[i];
    int ch = i / (NY * NX);
    int rem = i - ch * (NY * NX);
    int y = rem / NX;
    int x = rem - y * NX;
    bool f = true;
#pragma unroll
    for (int dy = -1; dy <= 1; dy++)
#pragma unroll
        for (int dx = -1; dx <= 1; dx++) {
            if (dy == 0 && dx == 0) continue;
            int yy = y + dy, xx = x + dx;
            if ((unsigned)yy < NY && (unsigned)xx < NX)
                f = f && (c >= hmp[ch * (NY * NX) + yy * NX + xx]);
        }
    g_flags[(size_t)b * KTOT + i] = f ? 1 : 0;
    unsigned bal = __ballot_sync(0xffffffffu, f);
    __shared__ int wc[32];
    int lane = threadIdx.x & 31, w = threadIdx.x >> 5;
    if (lane == 0) wc[w] = __popc(bal);
    __syncthreads();
    if (threadIdx.x == 0) {
        int s = 0;
        for (int k = 0; k < 32; k++) s += wc[k];
        g_bcount[bid] = s;
    }
}

/* ---------------- per-batch exclusive scan of 500 block counts ---------------- */
__global__ void scan_kernel() {
    __shared__ int s[512];
    int tid = threadIdx.x;
    for (int seg = 0; seg < 2; seg++) {
        int v = (tid < 500) ? g_bcount[seg * 500 + tid] : 0;
        s[tid] = v;
        __syncthreads();
        for (int off = 1; off < 512; off <<= 1) {
            int t = (tid >= off) ? s[tid - off] : 0;
            __syncthreads();
            s[tid] += t;
            __syncthreads();
        }
        if (tid < 500) g_boff[seg * 500 + tid] = s[tid] - v;
        __syncthreads();
    }
}

/* ---------------- scatter peak rows ---------------- */
__global__ void scatter_kernel(float* __restrict__ out) {
    int bid = blockIdx.x;
    int b = bid / 500;
    int i = (bid - b * 500) * 1024 + threadIdx.x;
    int f = g_flags[(size_t)b * KTOT + i];
    unsigned bal = __ballot_sync(0xffffffffu, f != 0);
    int lane = threadIdx.x & 31, w = threadIdx.x >> 5;
    __shared__ int wc[32], we[32];
    if (lane == 0) wc[w] = __popc(bal);
    __syncthreads();
    if (w == 0) {
        int v = wc[lane];
        int inc = v;
#pragma unroll
        for (int off = 1; off < 32; off <<= 1) {
            int t = __shfl_up_sync(0xffffffffu, inc, off);
            if (lane >= off) inc += t;
        }
        we[lane] = inc - v;
    }
    __syncthreads();
    if (f) {
        int rank = g_boff[bid] + we[w] + __popc(bal & ((1u << lane) - 1u));
        int ch = i / (NY * NX);
        int rem = i - ch * (NY * NX);
        int y = rem / NX;
        int x = rem - y * NX;
        size_t ob = ((size_t)b * KTOT + rank) * (size_t)NO;
        const float* q = g_xywh + ((size_t)b * (NY * NX) + y * NX + x) * 4;
        out[ob + 0] = q[0];
        out[ob + 1] = q[1];
        out[ob + 2] = q[2];
        out[ob + 3] = q[3];
        out[ob + 4] = g_hm[(size_t)b * KTOT + i];
        out[ob + 5 + ch] = 1.0f;
    }
}

/* ---------------- launcher ---------------- */
extern "C" void kernel_launch(void* const* d_in, const int* in_sizes, int n_in,
                              void* d_out, int out_size) {
    const float* x       = (const float*)d_in[0];
    const float* offsets = (const float*)d_in[1];
    const float* hm_w1   = (const float*)d_in[2];
    const float* hm_b1   = (const float*)d_in[3];
    const float* hm_w2   = (const float*)d_in[4];
    const float* hm_b2   = (const float*)d_in[5];
    const float* wh_w1   = (const float*)d_in[6];
    const float* wh_b1   = (const float*)d_in[7];
    const float* wh_w2   = (const float*)d_in[8];
    const float* wh_b2   = (const float*)d_in[9];
    const float* reg_w1  = (const float*)d_in[10];
    const float* reg_b1  = (const float*)d_in[11];
    const float* reg_w2  = (const float*)d_in[12];
    const float* reg_b2  = (const float*)d_in[13];
    float* out = (float*)d_out;

    cudaMemsetAsync(d_out, 0, (size_t)out_size * sizeof(float));

    prep_w1<<<(64 * OC3 * 9 + 255) / 256, 256>>>(hm_w1, wh_w1, reg_w1);
    prep_rest<<<(NU * 64 + 255) / 256, 256>>>(hm_b1, wh_b1, reg_b1,
                                              hm_w2, wh_w2, reg_w2,
                                              hm_b2, wh_b2, reg_b2);

    cudaFuncSetAttribute(conv_kernel, cudaFuncAttributeMaxDynamicSharedMemorySize, SMEM_BYTES);
    conv_kernel<<<400, 256, SMEM_BYTES>>>(x, offsets);

    mask_kernel<<<1000, 1024>>>();
    scan_kernel<<<1, 512>>>();
    scatter_kernel<<<1000, 1024>>>(out);
}

// round 2
// speedup vs baseline: 1.0106x; 1.0106x over previous
#include <cuda_runtime.h>
#include <math.h>
#include <stdint.h>

#define NBATCH 2
#define CHN 64
#define NY 80
#define NX 80
#define NCLS 80
#define KTOT (NCLS*NY*NX)   /* 512000 */
#define NO 85
#define OC3 192             /* 64 hm + 64 wh + 64 reg intermediate channels */
#define NU 84               /* stage2 outputs: 80 hm + 2 wh + 2 reg */

typedef unsigned long long ull;

/* ---------------- device scratch (static, no allocations) ---------------- */
__device__ float2 g_w1t2[64 * OC3 * 9];   /* [ci][oc(192)][9] broadcast weight pairs */
__device__ float g_w2[NU * 64];           /* merged 1x1 weights [u][ci] */
__device__ float g_b1[OC3];
__device__ float g_b2[NU];
__device__ float g_hm[NBATCH * KTOT];     /* sigmoid heatmap, [b][c][y][x] = scan order */
__device__ float g_xywh[NBATCH * NY * NX * 4];
__device__ unsigned char g_flags[NBATCH * KTOT];
__device__ int g_bcount[1000];
__device__ int g_boff[1000];

/* ---------------- f32x2 helpers ---------------- */
__device__ __forceinline__ void fma2(ull& d, ull a, ull b) {
    asm("fma.rn.f32x2 %0, %1, %2, %0;" : "+l"(d) : "l"(a), "l"(b));
}
__device__ __forceinline__ float2 unpack2(ull v) {
    float2 r;
    asm("mov.b64 {%0, %1}, %2;" : "=f"(r.x), "=f"(r.y) : "l"(v));
    return r;
}

/* ---------------- weight prep ---------------- */
__global__ void prep_w1(const float* __restrict__ hm, const float* __restrict__ wh,
                        const float* __restrict__ rg) {
    int idx = blockIdx.x * 256 + threadIdx.x;
    if (idx >= 64 * OC3 * 9) return;
    int ci = idx / (OC3 * 9);
    int r  = idx - ci * (OC3 * 9);
    int oc = r / 9;
    int k  = r - oc * 9;
    const float* src = (oc < 64) ? hm : (oc < 128) ? wh : rg;
    int o = oc & 63;
    float w = src[o * 576 + ci * 9 + k];
    g_w1t2[idx] = make_float2(w, w);
}

__global__ void prep_rest(const float* __restrict__ hm_b1, const float* __restrict__ wh_b1,
                          const float* __restrict__ reg_b1,
                          const float* __restrict__ hm_w2, const float* __restrict__ wh_w2,
                          const float* __restrict__ reg_w2,
                          const float* __restrict__ hm_b2, const float* __restrict__ wh_b2,
                          const float* __restrict__ reg_b2) {
    int t = blockIdx.x * 256 + threadIdx.x;
    if (t < OC3) g_b1[t] = (t < 64) ? hm_b1[t] : (t < 128) ? wh_b1[t - 64] : reg_b1[t - 128];
    if (t < NU)  g_b2[t] = (t < 80) ? hm_b2[t] : (t < 82) ? wh_b2[t - 80] : reg_b2[t - 82];
    if (t < NU * 64) {
        int u = t >> 6, ci = t & 63;
        g_w2[t] = (u < 80) ? hm_w2[u * 64 + ci]
                : (u < 82) ? wh_w2[(u - 80) * 64 + ci]
                           : reg_w2[(u - 82) * 64 + ci];
    }
}

/* ---------------- fused conv kernel ----------------
   Tile: 8x4 pixels per block, 256 threads, all 192 3x3-conv channels via
   packed f32x2 FMA, then fused 1x1 heads + sigmoid + bbox decode.        */
#define TTX 8
#define TTY 4
#define S_IN_SZ  (64 * 6 * 10)           /* 3840 floats, copy A */
#define O_INB    S_IN_SZ                 /* copy B = A shifted by +1 */
#define O_W      (2 * S_IN_SZ)           /* 7680: weight double-buffer (float2) */
#define W_SLAB   1728                    /* float2 per buffer = 192*9 */
#define S_W_FL   (2 * W_SLAB * 2)        /* 6912 floats */
#define O_U      (O_W + S_W_FL)          /* 14592 */
#define S_U_STR  193
#define S_U_SZ   (32 * S_U_STR)
#define O_W2     (O_U + S_U_SZ)          /* 20768 */
#define S_W2_STR 65
#define S_W2_SZ  (NU * S_W2_STR)
#define O_B1     (O_W2 + S_W2_SZ)
#define O_B2     (O_B1 + OC3)
#define SMEM_FLOATS (O_B2 + NU)
#define SMEM_BYTES  (SMEM_FLOATS * 4)

__global__ __launch_bounds__(256, 2) void conv_kernel(const float* __restrict__ x,
                                                      const float* __restrict__ offsets) {
    extern __shared__ float sm[];
    float* s_inA = sm;
    float* s_inB = sm + O_INB;
    float* s_wf  = sm + O_W;             /* float2 pairs, viewed as floats */
    float* s_u   = sm + O_U;
    float* s_w2  = sm + O_W2;
    float* s_b1  = sm + O_B1;
    float* s_b2  = sm + O_B2;

    int tid = threadIdx.x;
    int bid = blockIdx.x;
    int b = bid / 200;
    int t = bid - b * 200;
    int y0 = (t / 10) * TTY;
    int x0 = (t % 10) * TTX;

    for (int i = tid; i < OC3; i += 256) s_b1[i] = g_b1[i];
    for (int i = tid; i < NU; i += 256)  s_b2[i] = g_b2[i];
    for (int i = tid; i < NU * 64; i += 256) {
        int u = i >> 6, ci = i & 63;
        s_w2[u * S_W2_STR + ci] = g_w2[i];
    }

    const float* xb = x + (size_t)b * CHN * NY * NX;
    for (int i = tid; i < S_IN_SZ; i += 256) {
        int ci = i / 60;
        int r  = (i % 60) / 10;
        int c  = i % 10;
        int gy = y0 + r - 1;
        float va = 0.f, vb = 0.f;
        if ((unsigned)gy < NY) {
            int gxa = x0 + c - 1;
            int gxb = x0 + c;
            const float* rowp = xb + (ci * NY + gy) * NX;
            if ((unsigned)gxa < NX) va = rowp[gxa];
            if ((unsigned)gxb < NX) vb = rowp[gxb];
        }
        s_inA[i] = va;
        s_inB[i] = vb;
    }
    /* weight buffer 0 = ci 0 slab */
    {
        const float2* src = g_w1t2;
        float2* dst = (float2*)s_wf;
        for (int i = tid; i < W_SLAB; i += 256) dst[i] = src[i];
    }
    __syncthreads();

    int pxg = tid & 7;        /* 8 pixel groups: 4 rows x 2 col-quads */
    int ocg = tid >> 3;       /* 32 oc groups of 6 */
    int row = pxg >> 1;
    int c0  = (pxg & 1) * 4;

    ull acc0[6], acc1[6];     /* acc0 = px(c0,c0+1), acc1 = px(c0+2,c0+3) */
#pragma unroll
    for (int o = 0; o < 6; o++) { acc0[o] = 0ull; acc1[o] = 0ull; }

    float2 pf[7];
    for (int ci = 0; ci < 64; ci++) {
        int buf = ci & 1;
        if (ci + 1 < 64) {
            const float2* src = g_w1t2 + (ci + 1) * W_SLAB;
#pragma unroll
            for (int j = 0; j < 7; j++) {
                int idx = tid + j * 256;
                pf[j] = (idx < W_SLAB) ? src[idx] : make_float2(0.f, 0.f);
            }
        }
        /* load 15 input pairs: per row rr, pairs at offsets 0,1,2,3,4 */
        const float* sa = s_inA + ci * 60 + row * 10 + c0;
        const float* sb = s_inB + ci * 60 + row * 10 + c0;
        ull P[3][5];
#pragma unroll
        for (int rr = 0; rr < 3; rr++) {
            P[rr][0] = *(const ull*)(sa + rr * 10);
            P[rr][1] = *(const ull*)(sb + rr * 10);
            P[rr][2] = *(const ull*)(sa + rr * 10 + 2);
            P[rr][3] = *(const ull*)(sb + rr * 10 + 2);
            P[rr][4] = *(const ull*)(sa + rr * 10 + 4);
        }
        const float* wb = s_wf + buf * (W_SLAB * 2) + ocg * (6 * 18);
#pragma unroll
        for (int o = 0; o < 6; o++) {
            ull w[9];
#pragma unroll
            for (int k = 0; k < 9; k++) w[k] = *(const ull*)(wb + o * 18 + k * 2);
#pragma unroll
            for (int rr = 0; rr < 3; rr++) {
                fma2(acc0[o], P[rr][0], w[rr * 3 + 0]);
                fma2(acc1[o], P[rr][2], w[rr * 3 + 0]);
                fma2(acc0[o], P[rr][1], w[rr * 3 + 1]);
                fma2(acc1[o], P[rr][3], w[rr * 3 + 1]);
                fma2(acc0[o], P[rr][2], w[rr * 3 + 2]);
                fma2(acc1[o], P[rr][4], w[rr * 3 + 2]);
            }
        }
        if (ci + 1 < 64) {
            float2* dst = (float2*)s_wf + (buf ^ 1) * W_SLAB;
#pragma unroll
            for (int j = 0; j < 7; j++) {
                int idx = tid + j * 256;
                if (idx < W_SLAB) dst[idx] = pf[j];
            }
        }
        __syncthreads();
    }

    /* stash relu(conv3x3 + b1) intermediates */
#pragma unroll
    for (int o = 0; o < 6; o++) {
        int oc = ocg * 6 + o;
        float bia = s_b1[oc];
        float2 u0 = unpack2(acc0[o]);
        float2 u1 = unpack2(acc1[o]);
        int px = row * TTX + c0;
        s_u[(px + 0) * S_U_STR + oc] = fmaxf(u0.x + bia, 0.f);
        s_u[(px + 1) * S_U_STR + oc] = fmaxf(u0.y + bia, 0.f);
        s_u[(px + 2) * S_U_STR + oc] = fmaxf(u1.x + bia, 0.f);
        s_u[(px + 3) * S_U_STR + oc] = fmaxf(u1.y + bia, 0.f);
    }
    __syncthreads();

    /* stage 2: 1x1 convs + sigmoid / bbox decode. 21 groups of 4 outputs x 8 px-quads */
    if (tid < 168) {
        int pxq = tid & 7;
        int g   = tid >> 3;   /* 0..20 */
        float acc2[4][4];
#pragma unroll
        for (int s = 0; s < 4; s++)
#pragma unroll
            for (int p = 0; p < 4; p++) acc2[s][p] = 0.f;

        if (g < 20) {
            const float* w0 = s_w2 + (g * 4 + 0) * S_W2_STR;
            const float* w1 = s_w2 + (g * 4 + 1) * S_W2_STR;
            const float* w2 = s_w2 + (g * 4 + 2) * S_W2_STR;
            const float* w3 = s_w2 + (g * 4 + 3) * S_W2_STR;
#pragma unroll 4
            for (int ci = 0; ci < 64; ci++) {
                float v0 = w0[ci], v1 = w1[ci], v2 = w2[ci], v3 = w3[ci];
#pragma unroll
                for (int p = 0; p < 4; p++) {
                    float uv = s_u[(pxq * 4 + p) * S_U_STR + ci];
                    acc2[0][p] += uv * v0;
                    acc2[1][p] += uv * v1;
                    acc2[2][p] += uv * v2;
                    acc2[3][p] += uv * v3;
                }
            }
#pragma unroll
            for (int s = 0; s < 4; s++) {
                int u = g * 4 + s;
                float bia = s_b2[u];
#pragma unroll
                for (int p = 0; p < 4; p++) {
                    float v = acc2[s][p] + bia;
                    float sig = 1.f / (1.f + expf(-v));
                    int px = pxq * 4 + p;
                    int gy = y0 + (px >> 3), gx = x0 + (px & 7);
                    g_hm[b * KTOT + u * (NY * NX) + gy * NX + gx] = sig;
                }
            }
        } else {
            /* g==20: wh_x, wh_y, reg_x, reg_y */
            const float* w0 = s_w2 + 80 * S_W2_STR;
            const float* w1 = s_w2 + 81 * S_W2_STR;
            const float* w2 = s_w2 + 82 * S_W2_STR;
            const float* w3 = s_w2 + 83 * S_W2_STR;
#pragma unroll 4
            for (int ci = 0; ci < 64; ci++) {
                float v0 = w0[ci], v1 = w1[ci], v2 = w2[ci], v3 = w3[ci];
#pragma unroll
                for (int p = 0; p < 4; p++) {
                    float uw = s_u[(pxq * 4 + p) * S_U_STR + 64 + ci];
                    float ur = s_u[(pxq * 4 + p) * S_U_STR + 128 + ci];
                    acc2[0][p] += uw * v0;
                    acc2[1][p] += uw * v1;
                    acc2[2][p] += ur * v2;
                    acc2[3][p] += ur * v3;
                }
            }
            float offx = offsets[b * 3 + 1] * 2.f;
            float offy = offsets[b * 3 + 2] * 2.f;
#pragma unroll
            for (int p = 0; p < 4; p++) {
                int px = pxq * 4 + p;
                int gy = y0 + (px >> 3), gx = x0 + (px & 7);
                float whx = fmaxf(acc2[0][p] + s_b2[80], 0.f);
                float why = fmaxf(acc2[1][p] + s_b2[81], 0.f);
                float rgx = fmaxf(acc2[2][p] + s_b2[82], 0.f);
                float rgy = fmaxf(acc2[3][p] + s_b2[83], 0.f);
                float cx = ((float)gx + offx + rgx) * 4.f;
                float cy = ((float)gy + offy + rgy) * 4.f;
                float* q = g_xywh + ((size_t)b * (NY * NX) + gy * NX + gx) * 4;
                q[0] = cx; q[1] = cy; q[2] = whx * 4.f; q[3] = why * 4.f;
            }
        }
    }
}

/* ---------------- maxima mask + per-block counts ---------------- */
__global__ void mask_kernel() {
    int bid = blockIdx.x;
    int b = bid / 500;
    int i = (bid - b * 500) * 1024 + threadIdx.x;
    const float* hmp = g_hm + (size_t)b * KTOT;
    float c = hmp[i];
    int ch = i / (NY * NX);
    int rem = i - ch * (NY * NX);
    int y = rem / NX;
    int x = rem - y * NX;
    bool f = true;
#pragma unroll
    for (int dy = -1; dy <= 1; dy++)
#pragma unroll
        for (int dx = -1; dx <= 1; dx++) {
            if (dy == 0 && dx == 0) continue;
            int yy = y + dy, xx = x + dx;
            if ((unsigned)yy < NY && (unsigned)xx < NX)
                f = f && (c >= hmp[ch * (NY * NX) + yy * NX + xx]);
        }
    g_flags[(size_t)b * KTOT + i] = f ? 1 : 0;
    unsigned bal = __ballot_sync(0xffffffffu, f);
    __shared__ int wc[32];
    int lane = threadIdx.x & 31, w = threadIdx.x >> 5;
    if (lane == 0) wc[w] = __popc(bal);
    __syncthreads();
    if (threadIdx.x == 0) {
        int s = 0;
        for (int k = 0; k < 32; k++) s += wc[k];
        g_bcount[bid] = s;
    }
}

/* ---------------- per-batch exclusive scan of 500 block counts ---------------- */
__global__ void scan_kernel() {
    __shared__ int s[512];
    int tid = threadIdx.x;
    for (int seg = 0; seg < 2; seg++) {
        int v = (tid < 500) ? g_bcount[seg * 500 + tid] : 0;
        s[tid] = v;
        __syncthreads();
        for (int off = 1; off < 512; off <<= 1) {
            int t = (tid >= off) ? s[tid - off] : 0;
            __syncthreads();
            s[tid] += t;
            __syncthreads();
        }
        if (tid < 500) g_boff[seg * 500 + tid] = s[tid] - v;
        __syncthreads();
    }
}

/* ---------------- scatter peak rows ---------------- */
__global__ void scatter_kernel(float* __restrict__ out) {
    int bid = blockIdx.x;
    int b = bid / 500;
    int i = (bid - b * 500) * 1024 + threadIdx.x;
    int f = g_flags[(size_t)b * KTOT + i];
    unsigned bal = __ballot_sync(0xffffffffu, f != 0);
    int lane = threadIdx.x & 31, w = threadIdx.x >> 5;
    __shared__ int wc[32], we[32];
    if (lane == 0) wc[w] = __popc(bal);
    __syncthreads();
    if (w == 0) {
        int v = wc[lane];
        int inc = v;
#pragma unroll
        for (int off = 1; off < 32; off <<= 1) {
            int t = __shfl_up_sync(0xffffffffu, inc, off);
            if (lane >= off) inc += t;
        }
        we[lane] = inc - v;
    }
    __syncthreads();
    if (f) {
        int rank = g_boff[bid] + we[w] + __popc(bal & ((1u << lane) - 1u));
        int ch = i / (NY * NX);
        int rem = i - ch * (NY * NX);
        int y = rem / NX;
        int x = rem - y * NX;
        size_t ob = ((size_t)b * KTOT + rank) * (size_t)NO;
        const float* q = g_xywh + ((size_t)b * (NY * NX) + y * NX + x) * 4;
        out[ob + 0] = q[0];
        out[ob + 1] = q[1];
        out[ob + 2] = q[2];
        out[ob + 3] = q[3];
        out[ob + 4] = g_hm[(size_t)b * KTOT + i];
        out[ob + 5 + ch] = 1.0f;
    }
}

/* ---------------- launcher ---------------- */
extern "C" void kernel_launch(void* const* d_in, const int* in_sizes, int n_in,
                              void* d_out, int out_size) {
    const float* x       = (const float*)d_in[0];
    const float* offsets = (const float*)d_in[1];
    const float* hm_w1   = (const float*)d_in[2];
    const float* hm_b1   = (const float*)d_in[3];
    const float* hm_w2   = (const float*)d_in[4];
    const float* hm_b2   = (const float*)d_in[5];
    const float* wh_w1   = (const float*)d_in[6];
    const float* wh_b1   = (const float*)d_in[7];
    const float* wh_w2   = (const float*)d_in[8];
    const float* wh_b2   = (const float*)d_in[9];
    const float* reg_w1  = (const float*)d_in[10];
    const float* reg_b1  = (const float*)d_in[11];
    const float* reg_w2  = (const float*)d_in[12];
    const float* reg_b2  = (const float*)d_in[13];
    float* out = (float*)d_out;

    /* fork: big output memset runs on a side stream, joined before scatter */
    cudaStream_t side;
    cudaEvent_t e1, e2;
    cudaStreamCreateWithFlags(&side, cudaStreamNonBlocking);
    cudaEventCreateWithFlags(&e1, cudaEventDisableTiming);
    cudaEventCreateWithFlags(&e2, cudaEventDisableTiming);

    cudaEventRecord(e1, 0);
    cudaStreamWaitEvent(side, e1, 0);
    cudaMemsetAsync(d_out, 0, (size_t)out_size * sizeof(float), side);
    cudaEventRecord(e2, side);

    prep_w1<<<(64 * OC3 * 9 + 255) / 256, 256>>>(hm_w1, wh_w1, reg_w1);
    prep_rest<<<(NU * 64 + 255) / 256, 256>>>(hm_b1, wh_b1, reg_b1,
                                              hm_w2, wh_w2, reg_w2,
                                              hm_b2, wh_b2, reg_b2);

    cudaFuncSetAttribute(conv_kernel, cudaFuncAttributeMaxDynamicSharedMemorySize, SMEM_BYTES);
    conv_kernel<<<400, 256, SMEM_BYTES>>>(x, offsets);

    mask_kernel<<<1000, 1024>>>();
    scan_kernel<<<1, 512>>>();

    cudaStreamWaitEvent(0, e2, 0);
    scatter_kernel<<<1000, 1024>>>(out);
}

// round 3
// speedup vs baseline: 1.0301x; 1.0192x over previous
#include <cuda_runtime.h>
#include <math.h>
#include <stdint.h>

#define NBATCH 2
#define CHN 64
#define NY 80
#define NX 80
#define NCLS 80
#define KTOT (NCLS*NY*NX)   /* 512000 */
#define NO 85
#define OC3 192             /* 64 hm + 64 wh + 64 reg intermediate channels */
#define NU 84               /* stage2 outputs: 80 hm + 2 wh + 2 reg */
#define ELEMS_PER_BATCH (KTOT * NO)      /* 43,520,000 */

typedef unsigned long long ull;

/* ---------------- device scratch (static, no allocations) ---------------- */
__device__ float2 g_w1t2[64 * OC3 * 9];   /* [ci][oc(192)][9] broadcast weight pairs */
__device__ float g_w2[NU * 64];           /* merged 1x1 weights [u][ci] */
__device__ float g_b1[OC3];
__device__ float g_b2[NU];
__device__ float g_hm[NBATCH * KTOT];     /* sigmoid heatmap, [b][c][y][x] = scan order */
__device__ float g_xywh[NBATCH * NY * NX * 4];
__device__ unsigned char g_flags[NBATCH * KTOT];
__device__ int g_bcount[1000];
__device__ int g_boff[1000];
__device__ int g_total[NBATCH];
__device__ float g_rows[NBATCH * KTOT * 8];  /* compact rows: x,y,w,h,score,ch,-,- */

/* ---------------- f32x2 helpers ---------------- */
__device__ __forceinline__ void fma2(ull& d, ull a, ull b) {
    asm("fma.rn.f32x2 %0, %1, %2, %0;" : "+l"(d) : "l"(a), "l"(b));
}
__device__ __forceinline__ float2 unpack2(ull v) {
    float2 r;
    asm("mov.b64 {%0, %1}, %2;" : "=f"(r.x), "=f"(r.y) : "l"(v));
    return r;
}

/* ---------------- weight prep ---------------- */
__global__ void prep_w1(const float* __restrict__ hm, const float* __restrict__ wh,
                        const float* __restrict__ rg) {
    int idx = blockIdx.x * 256 + threadIdx.x;
    if (idx >= 64 * OC3 * 9) return;
    int ci = idx / (OC3 * 9);
    int r  = idx - ci * (OC3 * 9);
    int oc = r / 9;
    int k  = r - oc * 9;
    const float* src = (oc < 64) ? hm : (oc < 128) ? wh : rg;
    int o = oc & 63;
    float w = src[o * 576 + ci * 9 + k];
    g_w1t2[idx] = make_float2(w, w);
}

__global__ void prep_rest(const float* __restrict__ hm_b1, const float* __restrict__ wh_b1,
                          const float* __restrict__ reg_b1,
                          const float* __restrict__ hm_w2, const float* __restrict__ wh_w2,
                          const float* __restrict__ reg_w2,
                          const float* __restrict__ hm_b2, const float* __restrict__ wh_b2,
                          const float* __restrict__ reg_b2) {
    int t = blockIdx.x * 256 + threadIdx.x;
    if (t < OC3) g_b1[t] = (t < 64) ? hm_b1[t] : (t < 128) ? wh_b1[t - 64] : reg_b1[t - 128];
    if (t < NU)  g_b2[t] = (t < 80) ? hm_b2[t] : (t < 82) ? wh_b2[t - 80] : reg_b2[t - 82];
    if (t < NU * 64) {
        int u = t >> 6, ci = t & 63;
        g_w2[t] = (u < 80) ? hm_w2[u * 64 + ci]
                : (u < 82) ? wh_w2[(u - 80) * 64 + ci]
                           : reg_w2[(u - 82) * 64 + ci];
    }
}

/* ---------------- fused conv kernel (unchanged from R2) ---------------- */
#define TTX 8
#define TTY 4
#define S_IN_SZ  (64 * 6 * 10)
#define O_INB    S_IN_SZ
#define O_W      (2 * S_IN_SZ)
#define W_SLAB   1728
#define S_W_FL   (2 * W_SLAB * 2)
#define O_U      (O_W + S_W_FL)
#define S_U_STR  193
#define S_U_SZ   (32 * S_U_STR)
#define O_W2     (O_U + S_U_SZ)
#define S_W2_STR 65
#define S_W2_SZ  (NU * S_W2_STR)
#define O_B1     (O_W2 + S_W2_SZ)
#define O_B2     (O_B1 + OC3)
#define SMEM_FLOATS (O_B2 + NU)
#define SMEM_BYTES  (SMEM_FLOATS * 4)

__global__ __launch_bounds__(256, 2) void conv_kernel(const float* __restrict__ x,
                                                      const float* __restrict__ offsets) {
    extern __shared__ float sm[];
    float* s_inA = sm;
    float* s_inB = sm + O_INB;
    float* s_wf  = sm + O_W;
    float* s_u   = sm + O_U;
    float* s_w2  = sm + O_W2;
    float* s_b1  = sm + O_B1;
    float* s_b2  = sm + O_B2;

    int tid = threadIdx.x;
    int bid = blockIdx.x;
    int b = bid / 200;
    int t = bid - b * 200;
    int y0 = (t / 10) * TTY;
    int x0 = (t % 10) * TTX;

    for (int i = tid; i < OC3; i += 256) s_b1[i] = g_b1[i];
    for (int i = tid; i < NU; i += 256)  s_b2[i] = g_b2[i];
    for (int i = tid; i < NU * 64; i += 256) {
        int u = i >> 6, ci = i & 63;
        s_w2[u * S_W2_STR + ci] = g_w2[i];
    }

    const float* xb = x + (size_t)b * CHN * NY * NX;
    for (int i = tid; i < S_IN_SZ; i += 256) {
        int ci = i / 60;
        int r  = (i % 60) / 10;
        int c  = i % 10;
        int gy = y0 + r - 1;
        float va = 0.f, vb = 0.f;
        if ((unsigned)gy < NY) {
            int gxa = x0 + c - 1;
            int gxb = x0 + c;
            const float* rowp = xb + (ci * NY + gy) * NX;
            if ((unsigned)gxa < NX) va = rowp[gxa];
            if ((unsigned)gxb < NX) vb = rowp[gxb];
        }
        s_inA[i] = va;
        s_inB[i] = vb;
    }
    {
        const float2* src = g_w1t2;
        float2* dst = (float2*)s_wf;
        for (int i = tid; i < W_SLAB; i += 256) dst[i] = src[i];
    }
    __syncthreads();

    int pxg = tid & 7;
    int ocg = tid >> 3;
    int row = pxg >> 1;
    int c0  = (pxg & 1) * 4;

    ull acc0[6], acc1[6];
#pragma unroll
    for (int o = 0; o < 6; o++) { acc0[o] = 0ull; acc1[o] = 0ull; }

    float2 pf[7];
    for (int ci = 0; ci < 64; ci++) {
        int buf = ci & 1;
        if (ci + 1 < 64) {
            const float2* src = g_w1t2 + (ci + 1) * W_SLAB;
#pragma unroll
            for (int j = 0; j < 7; j++) {
                int idx = tid + j * 256;
                pf[j] = (idx < W_SLAB) ? src[idx] : make_float2(0.f, 0.f);
            }
        }
        const float* sa = s_inA + ci * 60 + row * 10 + c0;
        const float* sb = s_inB + ci * 60 + row * 10 + c0;
        ull P[3][5];
#pragma unroll
        for (int rr = 0; rr < 3; rr++) {
            P[rr][0] = *(const ull*)(sa + rr * 10);
            P[rr][1] = *(const ull*)(sb + rr * 10);
            P[rr][2] = *(const ull*)(sa + rr * 10 + 2);
            P[rr][3] = *(const ull*)(sb + rr * 10 + 2);
            P[rr][4] = *(const ull*)(sa + rr * 10 + 4);
        }
        const float* wb = s_wf + buf * (W_SLAB * 2) + ocg * (6 * 18);
#pragma unroll
        for (int o = 0; o < 6; o++) {
            ull w[9];
#pragma unroll
            for (int k = 0; k < 9; k++) w[k] = *(const ull*)(wb + o * 18 + k * 2);
#pragma unroll
            for (int rr = 0; rr < 3; rr++) {
                fma2(acc0[o], P[rr][0], w[rr * 3 + 0]);
                fma2(acc1[o], P[rr][2], w[rr * 3 + 0]);
                fma2(acc0[o], P[rr][1], w[rr * 3 + 1]);
                fma2(acc1[o], P[rr][3], w[rr * 3 + 1]);
                fma2(acc0[o], P[rr][2], w[rr * 3 + 2]);
                fma2(acc1[o], P[rr][4], w[rr * 3 + 2]);
            }
        }
        if (ci + 1 < 64) {
            float2* dst = (float2*)s_wf + (buf ^ 1) * W_SLAB;
#pragma unroll
            for (int j = 0; j < 7; j++) {
                int idx = tid + j * 256;
                if (idx < W_SLAB) dst[idx] = pf[j];
            }
        }
        __syncthreads();
    }

#pragma unroll
    for (int o = 0; o < 6; o++) {
        int oc = ocg * 6 + o;
        float bia = s_b1[oc];
        float2 u0 = unpack2(acc0[o]);
        float2 u1 = unpack2(acc1[o]);
        int px = row * TTX + c0;
        s_u[(px + 0) * S_U_STR + oc] = fmaxf(u0.x + bia, 0.f);
        s_u[(px + 1) * S_U_STR + oc] = fmaxf(u0.y + bia, 0.f);
        s_u[(px + 2) * S_U_STR + oc] = fmaxf(u1.x + bia, 0.f);
        s_u[(px + 3) * S_U_STR + oc] = fmaxf(u1.y + bia, 0.f);
    }
    __syncthreads();

    if (tid < 168) {
        int pxq = tid & 7;
        int g   = tid >> 3;
        float acc2[4][4];
#pragma unroll
        for (int s = 0; s < 4; s++)
#pragma unroll
            for (int p = 0; p < 4; p++) acc2[s][p] = 0.f;

        if (g < 20) {
            const float* w0 = s_w2 + (g * 4 + 0) * S_W2_STR;
            const float* w1 = s_w2 + (g * 4 + 1) * S_W2_STR;
            const float* w2 = s_w2 + (g * 4 + 2) * S_W2_STR;
            const float* w3 = s_w2 + (g * 4 + 3) * S_W2_STR;
#pragma unroll 4
            for (int ci = 0; ci < 64; ci++) {
                float v0 = w0[ci], v1 = w1[ci], v2 = w2[ci], v3 = w3[ci];
#pragma unroll
                for (int p = 0; p < 4; p++) {
                    float uv = s_u[(pxq * 4 + p) * S_U_STR + ci];
                    acc2[0][p] += uv * v0;
                    acc2[1][p] += uv * v1;
                    acc2[2][p] += uv * v2;
                    acc2[3][p] += uv * v3;
                }
            }
#pragma unroll
            for (int s = 0; s < 4; s++) {
                int u = g * 4 + s;
                float bia = s_b2[u];
#pragma unroll
                for (int p = 0; p < 4; p++) {
                    float v = acc2[s][p] + bia;
                    float sig = 1.f / (1.f + expf(-v));
                    int px = pxq * 4 + p;
                    int gy = y0 + (px >> 3), gx = x0 + (px & 7);
                    g_hm[b * KTOT + u * (NY * NX) + gy * NX + gx] = sig;
                }
            }
        } else {
            const float* w0 = s_w2 + 80 * S_W2_STR;
            const float* w1 = s_w2 + 81 * S_W2_STR;
            const float* w2 = s_w2 + 82 * S_W2_STR;
            const float* w3 = s_w2 + 83 * S_W2_STR;
#pragma unroll 4
            for (int ci = 0; ci < 64; ci++) {
                float v0 = w0[ci], v1 = w1[ci], v2 = w2[ci], v3 = w3[ci];
#pragma unroll
                for (int p = 0; p < 4; p++) {
                    float uw = s_u[(pxq * 4 + p) * S_U_STR + 64 + ci];
                    float ur = s_u[(pxq * 4 + p) * S_U_STR + 128 + ci];
                    acc2[0][p] += uw * v0;
                    acc2[1][p] += uw * v1;
                    acc2[2][p] += ur * v2;
                    acc2[3][p] += ur * v3;
                }
            }
            float offx = offsets[b * 3 + 1] * 2.f;
            float offy = offsets[b * 3 + 2] * 2.f;
#pragma unroll
            for (int p = 0; p < 4; p++) {
                int px = pxq * 4 + p;
                int gy = y0 + (px >> 3), gx = x0 + (px & 7);
                float whx = fmaxf(acc2[0][p] + s_b2[80], 0.f);
                float why = fmaxf(acc2[1][p] + s_b2[81], 0.f);
                float rgx = fmaxf(acc2[2][p] + s_b2[82], 0.f);
                float rgy = fmaxf(acc2[3][p] + s_b2[83], 0.f);
                float cx = ((float)gx + offx + rgx) * 4.f;
                float cy = ((float)gy + offy + rgy) * 4.f;
                float* q = g_xywh + ((size_t)b * (NY * NX) + gy * NX + gx) * 4;
                q[0] = cx; q[1] = cy; q[2] = whx * 4.f; q[3] = why * 4.f;
            }
        }
    }
}

/* ---------------- maxima mask + per-block counts ---------------- */
__global__ void mask_kernel() {
    int bid = blockIdx.x;
    int b = bid / 500;
    int i = (bid - b * 500) * 1024 + threadIdx.x;
    const float* hmp = g_hm + (size_t)b * KTOT;
    float c = hmp[i];
    int ch = i / (NY * NX);
    int rem = i - ch * (NY * NX);
    int y = rem / NX;
    int x = rem - y * NX;
    bool f = true;
#pragma unroll
    for (int dy = -1; dy <= 1; dy++)
#pragma unroll
        for (int dx = -1; dx <= 1; dx++) {
            if (dy == 0 && dx == 0) continue;
            int yy = y + dy, xx = x + dx;
            if ((unsigned)yy < NY && (unsigned)xx < NX)
                f = f && (c >= hmp[ch * (NY * NX) + yy * NX + xx]);
        }
    g_flags[(size_t)b * KTOT + i] = f ? 1 : 0;
    unsigned bal = __ballot_sync(0xffffffffu, f);
    __shared__ int wc[32];
    int lane = threadIdx.x & 31, w = threadIdx.x >> 5;
    if (lane == 0) wc[w] = __popc(bal);
    __syncthreads();
    if (threadIdx.x == 0) {
        int s = 0;
        for (int k = 0; k < 32; k++) s += wc[k];
        g_bcount[bid] = s;
    }
}

/* ---------------- per-batch exclusive scan of 500 block counts ---------------- */
__global__ void scan_kernel() {
    __shared__ int s[512];
    int tid = threadIdx.x;
    for (int seg = 0; seg < 2; seg++) {
        int v = (tid < 500) ? g_bcount[seg * 500 + tid] : 0;
        s[tid] = v;
        __syncthreads();
        for (int off = 1; off < 512; off <<= 1) {
            int t = (tid >= off) ? s[tid - off] : 0;
            __syncthreads();
            s[tid] += t;
            __syncthreads();
        }
        if (tid < 500) g_boff[seg * 500 + tid] = s[tid] - v;
        if (tid == 499) g_total[seg] = s[499];
        __syncthreads();
    }
}

/* ---------------- compact peak rows into dense table ---------------- */
__global__ void compact_kernel() {
    int bid = blockIdx.x;
    int b = bid / 500;
    int i = (bid - b * 500) * 1024 + threadIdx.x;
    int f = g_flags[(size_t)b * KTOT + i];
    unsigned bal = __ballot_sync(0xffffffffu, f != 0);
    int lane = threadIdx.x & 31, w = threadIdx.x >> 5;
    __shared__ int wc[32], we[32];
    if (lane == 0) wc[w] = __popc(bal);
    __syncthreads();
    if (w == 0) {
        int v = wc[lane];
        int inc = v;
#pragma unroll
        for (int off = 1; off < 32; off <<= 1) {
            int t = __shfl_up_sync(0xffffffffu, inc, off);
            if (lane >= off) inc += t;
        }
        we[lane] = inc - v;
    }
    __syncthreads();
    if (f) {
        int rank = g_boff[bid] + we[w] + __popc(bal & ((1u << lane) - 1u));
        int ch = i / (NY * NX);
        int rem = i - ch * (NY * NX);
        int y = rem / NX;
        int x = rem - y * NX;
        const float* q = g_xywh + ((size_t)b * (NY * NX) + y * NX + x) * 4;
        float* rd = g_rows + ((size_t)b * KTOT + rank) * 8;
        float4 lo = make_float4(q[0], q[1], q[2], q[3]);
        float4 hi = make_float4(g_hm[(size_t)b * KTOT + i], (float)ch, 0.f, 0.f);
        *(float4*)(rd)     = lo;
        *(float4*)(rd + 4) = hi;
    }
}

/* ---------------- fill: write entire output exactly once ----------------
   87,040,000 floats = 21,760,000 float4. Rows r < count[b] reconstructed
   from g_rows; everything else streams zeros.                             */
#define TOTAL4 (NBATCH * ELEMS_PER_BATCH / 4)   /* 21,760,000 */

__global__ __launch_bounds__(256) void fill_kernel(float4* __restrict__ out4) {
    int base = blockIdx.x * 1024 + threadIdx.x;
#pragma unroll
    for (int k = 0; k < 4; k++) {
        int q = base + k * 256;
        if (q >= TOTAL4) continue;
        int f0 = q * 4;                            /* first flat float index */
        int b = (f0 >= ELEMS_PER_BATCH) ? 1 : 0;
        int e = f0 - b * ELEMS_PER_BATCH;
        int r0 = e / NO;
        int c0 = e - r0 * NO;
        int cnt = g_total[b];
        if (r0 >= cnt) {
            out4[q] = make_float4(0.f, 0.f, 0.f, 0.f);
        } else {
            float v[4];
#pragma unroll
            for (int j = 0; j < 4; j++) {
                int c = c0 + j;
                int r = r0;
                if (c >= NO) { c -= NO; r++; }
                float val = 0.f;
                if (r < cnt) {
                    const float* rd = g_rows + ((size_t)b * KTOT + r) * 8;
                    if (c < 5) val = __ldg(rd + c);
                    else {
                        int ch = (int)__ldg(rd + 5);
                        val = (c == 5 + ch) ? 1.0f : 0.f;
                    }
                }
                v[j] = val;
            }
            out4[q] = make_float4(v[0], v[1], v[2], v[3]);
        }
    }
}

/* ---------------- launcher ---------------- */
extern "C" void kernel_launch(void* const* d_in, const int* in_sizes, int n_in,
                              void* d_out, int out_size) {
    const float* x       = (const float*)d_in[0];
    const float* offsets = (const float*)d_in[1];
    const float* hm_w1   = (const float*)d_in[2];
    const float* hm_b1   = (const float*)d_in[3];
    const float* hm_w2   = (const float*)d_in[4];
    const float* hm_b2   = (const float*)d_in[5];
    const float* wh_w1   = (const float*)d_in[6];
    const float* wh_b1   = (const float*)d_in[7];
    const float* wh_w2   = (const float*)d_in[8];
    const float* wh_b2   = (const float*)d_in[9];
    const float* reg_w1  = (const float*)d_in[10];
    const float* reg_b1  = (const float*)d_in[11];
    const float* reg_w2  = (const float*)d_in[12];
    const float* reg_b2  = (const float*)d_in[13];

    prep_w1<<<(64 * OC3 * 9 + 255) / 256, 256>>>(hm_w1, wh_w1, reg_w1);
    prep_rest<<<(NU * 64 + 255) / 256, 256>>>(hm_b1, wh_b1, reg_b1,
                                              hm_w2, wh_w2, reg_w2,
                                              hm_b2, wh_b2, reg_b2);

    cudaFuncSetAttribute(conv_kernel, cudaFuncAttributeMaxDynamicSharedMemorySize, SMEM_BYTES);
    conv_kernel<<<400, 256, SMEM_BYTES>>>(x, offsets);

    mask_kernel<<<1000, 1024>>>();
    scan_kernel<<<1, 512>>>();
    compact_kernel<<<1000, 1024>>>();

    fill_kernel<<<(TOTAL4 + 1023) / 1024, 256>>>((float4*)d_out);
}

// round 4
// speedup vs baseline: 1.1636x; 1.1297x over previous
#include <cuda_runtime.h>
#include <math.h>
#include <stdint.h>

#define NBATCH 2
#define CHN 64
#define NY 80
#define NX 80
#define NCLS 80
#define KTOT (NCLS*NY*NX)   /* 512000 */
#define NO 85
#define OC3 192             /* 64 hm + 64 wh + 64 reg intermediate channels */
#define NU 84               /* stage2 outputs: 80 hm + 2 wh + 2 reg */
#define ELEMS_PER_BATCH (KTOT * NO)      /* 43,520,000 */

typedef unsigned long long ull;

/* ---------------- device scratch (static, no allocations) ---------------- */
__device__ float2 g_w1t2[64 * OC3 * 9];   /* [ci][oc(192)][9] broadcast weight pairs */
__device__ float g_w2[NU * 64];           /* merged 1x1 weights [u][ci] */
__device__ float g_b1[OC3];
__device__ float g_b2[NU];
__device__ float g_hm[NBATCH * KTOT];     /* sigmoid heatmap, [b][c][y][x] = scan order */
__device__ float g_xywh[NBATCH * NY * NX * 4];
__device__ unsigned char g_flags[NBATCH * KTOT];
__device__ int g_bcount[1000];
__device__ int g_boff[1000];
__device__ int g_total[NBATCH];
__device__ float g_rows[NBATCH * KTOT * 8];  /* compact rows: x,y,w,h,score,ch,-,- */

/* ---------------- helpers ---------------- */
__device__ __forceinline__ void fma2(ull& d, ull a, ull b) {
    asm("fma.rn.f32x2 %0, %1, %2, %0;" : "+l"(d) : "l"(a), "l"(b));
}
__device__ __forceinline__ float2 unpack2(ull v) {
    float2 r;
    asm("mov.b64 {%0, %1}, %2;" : "=f"(r.x), "=f"(r.y) : "l"(v));
    return r;
}
__device__ __forceinline__ ull pack2f(float lo, float hi) {
    ull r;
    asm("mov.b64 %0, {%1, %2};" : "=l"(r) : "f"(lo), "f"(hi));
    return r;
}
__device__ __forceinline__ void cp_async16(uint32_t s, const void* g) {
    asm volatile("cp.async.cg.shared.global [%0], [%1], 16;" :: "r"(s), "l"(g));
}
__device__ __forceinline__ void cp_commit() {
    asm volatile("cp.async.commit_group;");
}
__device__ __forceinline__ void cp_wait0() {
    asm volatile("cp.async.wait_group 0;");
}
__device__ __forceinline__ uint32_t smem_u32(const void* p) {
    return (uint32_t)__cvta_generic_to_shared(p);
}

/* ---------------- weight prep ---------------- */
__global__ void prep_w1(const float* __restrict__ hm, const float* __restrict__ wh,
                        const float* __restrict__ rg) {
    int idx = blockIdx.x * 256 + threadIdx.x;
    if (idx >= 64 * OC3 * 9) return;
    int ci = idx / (OC3 * 9);
    int r  = idx - ci * (OC3 * 9);
    int oc = r / 9;
    int k  = r - oc * 9;
    const float* src = (oc < 64) ? hm : (oc < 128) ? wh : rg;
    int o = oc & 63;
    float w = src[o * 576 + ci * 9 + k];
    g_w1t2[idx] = make_float2(w, w);
}

__global__ void prep_rest(const float* __restrict__ hm_b1, const float* __restrict__ wh_b1,
                          const float* __restrict__ reg_b1,
                          const float* __restrict__ hm_w2, const float* __restrict__ wh_w2,
                          const float* __restrict__ reg_w2,
                          const float* __restrict__ hm_b2, const float* __restrict__ wh_b2,
                          const float* __restrict__ reg_b2) {
    int t = blockIdx.x * 256 + threadIdx.x;
    if (t < OC3) g_b1[t] = (t < 64) ? hm_b1[t] : (t < 128) ? wh_b1[t - 64] : reg_b1[t - 128];
    if (t < NU)  g_b2[t] = (t < 80) ? hm_b2[t] : (t < 82) ? wh_b2[t - 80] : reg_b2[t - 82];
    if (t < NU * 64) {
        int u = t >> 6, ci = t & 63;
        g_w2[t] = (u < 80) ? hm_w2[u * 64 + ci]
                : (u < 82) ? wh_w2[(u - 80) * 64 + ci]
                           : reg_w2[(u - 82) * 64 + ci];
    }
}

/* ---------------- fused conv kernel ----------------
   Tile 8x4 px, 256 threads, occupancy 3.  Thread = (row, ocg):
   row = tid&3, ocg = tid>>2 -> 3 oc, 4 pixel-pairs (one full row).
   Main-loop smem: input tile [64][6][12] + double-buffered weight slab
   (cp.async streamed).  Post-loop smem (aliased): s_u + s_w2 + s_b2.   */
#define TTX 8
#define TTY 4
#define S_IN_FL   (64 * 6 * 12)      /* 4608 floats, padded row stride 12 */
#define O_WS      S_IN_FL            /* weight slabs at 4608 */
#define W_SLAB_FL (OC3 * 9 * 2)      /* 3456 floats per buffer */
#define W_CHUNKS  (OC3 * 9 * 8 / 16) /* 864 cp.async 16B chunks per slab */
#define MAIN_FL   (O_WS + 2 * W_SLAB_FL)   /* 11520 */
/* post-loop region (aliased from offset 0) */
#define S_U_STR   193
#define S_U_FL    (32 * S_U_STR)     /* 6176 */
#define O_W2      S_U_FL
#define S_W2_STR  65
#define S_W2_FL   (NU * S_W2_STR)    /* 5460 */
#define O_B2      (O_W2 + S_W2_FL)
#define POST_FL   (O_B2 + NU)        /* 11720 */
#define SMEM_FL   (POST_FL > MAIN_FL ? POST_FL : MAIN_FL)
#define SMEM_BYTES (SMEM_FL * 4)

__global__ __launch_bounds__(256, 3) void conv_kernel(const float* __restrict__ x,
                                                      const float* __restrict__ offsets) {
    extern __shared__ float sm[];
    float* s_in = sm;
    float* s_w  = sm + O_WS;

    int tid = threadIdx.x;
    int bid = blockIdx.x;
    int b = bid / 200;
    int t = bid - b * 200;
    int y0 = (t / 10) * TTY;
    int x0 = (t % 10) * TTX;

    int r   = tid & 3;        /* output row within tile */
    int ocg = tid >> 2;       /* 0..63, 3 oc each */

    /* biases for my 3 oc held in registers */
    float b1v[3];
#pragma unroll
    for (int o = 0; o < 3; o++) b1v[o] = g_b1[ocg * 3 + o];

    /* kick cp.async for ci=0 weight slab into buffer 0 */
    {
        const char* src = (const char*)(g_w1t2);
        uint32_t dst = smem_u32(s_w);
        for (int j = tid; j < W_CHUNKS; j += 256)
            cp_async16(dst + j * 16, src + j * 16);
        cp_commit();
    }

    /* input tile [64][6][12] (cols 0..9 valid) */
    const float* xb = x + (size_t)b * CHN * NY * NX;
    for (int i = tid; i < 64 * 60; i += 256) {
        int ci = i / 60;
        int rem = i - ci * 60;
        int rr = rem / 10;
        int c  = rem - rr * 10;
        int gy = y0 + rr - 1;
        int gx = x0 + c - 1;
        float v = 0.f;
        if ((unsigned)gy < NY && (unsigned)gx < NX) v = xb[(ci * NY + gy) * NX + gx];
        s_in[ci * 72 + rr * 12 + c] = v;
    }
    cp_wait0();
    __syncthreads();

    ull acc[3][4];
#pragma unroll
    for (int o = 0; o < 3; o++)
#pragma unroll
        for (int c = 0; c < 4; c++) acc[o][c] = 0ull;

    for (int ci = 0; ci < 64; ci++) {
        int buf = ci & 1;
        if (ci + 1 < 64) {
            const char* src = (const char*)(g_w1t2 + (ci + 1) * (OC3 * 9));
            uint32_t dst = smem_u32(s_w + (buf ^ 1) * W_SLAB_FL);
            for (int j = tid; j < W_CHUNKS; j += 256)
                cp_async16(dst + j * 16, src + j * 16);
            cp_commit();
        }
        const float* wbuf = s_w + buf * W_SLAB_FL;
#pragma unroll
        for (int hr = 0; hr < 3; hr++) {
            const float* rowp = s_in + ci * 72 + (r + hr) * 12;
            float4 q0 = *(const float4*)rowp;
            float4 q1 = *(const float4*)(rowp + 4);
            float2 q2 = *(const float2*)(rowp + 8);
            ull PA[5], PB[4];
            PA[0] = pack2f(q0.x, q0.y);
            PA[1] = pack2f(q0.z, q0.w);
            PA[2] = pack2f(q1.x, q1.y);
            PA[3] = pack2f(q1.z, q1.w);
            PA[4] = pack2f(q2.x, q2.y);
            PB[0] = pack2f(q0.y, q0.z);
            PB[1] = pack2f(q0.w, q1.x);
            PB[2] = pack2f(q1.y, q1.z);
            PB[3] = pack2f(q1.w, q2.x);
#pragma unroll
            for (int o = 0; o < 3; o++) {
                const float* wp = wbuf + (ocg * 27 + o * 9 + hr * 3) * 2;
                ull w0 = *(const ull*)wp;
                ull w1 = *(const ull*)(wp + 2);
                ull w2 = *(const ull*)(wp + 4);
#pragma unroll
                for (int c = 0; c < 4; c++) {
                    fma2(acc[o][c], PA[c], w0);
                    fma2(acc[o][c], PB[c], w1);
                    fma2(acc[o][c], PA[c + 1], w2);
                }
            }
        }
        cp_wait0();
        __syncthreads();
    }

    /* ---- post-loop: alias smem to {s_u, s_w2, s_b2} ---- */
    float* s_u  = sm;
    float* s_w2 = sm + O_W2;
    float* s_b2 = sm + O_B2;

    /* stash relu(conv + b1): px = r*8 + 2c (+1) */
#pragma unroll
    for (int o = 0; o < 3; o++) {
        int oc = ocg * 3 + o;
#pragma unroll
        for (int c = 0; c < 4; c++) {
            float2 u = unpack2(acc[o][c]);
            int px = r * TTX + 2 * c;
            s_u[px * S_U_STR + oc]       = fmaxf(u.x + b1v[o], 0.f);
            s_u[(px + 1) * S_U_STR + oc] = fmaxf(u.y + b1v[o], 0.f);
        }
    }
    /* load 1x1 weights + biases into post region */
    for (int i = tid; i < NU * 64; i += 256) {
        int u = i >> 6, ci = i & 63;
        s_w2[u * S_W2_STR + ci] = g_w2[i];
    }
    for (int i = tid; i < NU; i += 256) s_b2[i] = g_b2[i];
    __syncthreads();

    /* stage 2: 1x1 convs + sigmoid / bbox decode. 21 groups x 8 px-quads */
    if (tid < 168) {
        int pxq = tid & 7;
        int g   = tid >> 3;
        float acc2[4][4];
#pragma unroll
        for (int s = 0; s < 4; s++)
#pragma unroll
            for (int p = 0; p < 4; p++) acc2[s][p] = 0.f;

        if (g < 20) {
            const float* w0 = s_w2 + (g * 4 + 0) * S_W2_STR;
            const float* w1 = s_w2 + (g * 4 + 1) * S_W2_STR;
            const float* w2 = s_w2 + (g * 4 + 2) * S_W2_STR;
            const float* w3 = s_w2 + (g * 4 + 3) * S_W2_STR;
#pragma unroll 4
            for (int ci = 0; ci < 64; ci++) {
                float v0 = w0[ci], v1 = w1[ci], v2 = w2[ci], v3 = w3[ci];
#pragma unroll
                for (int p = 0; p < 4; p++) {
                    float uv = s_u[(pxq * 4 + p) * S_U_STR + ci];
                    acc2[0][p] += uv * v0;
                    acc2[1][p] += uv * v1;
                    acc2[2][p] += uv * v2;
                    acc2[3][p] += uv * v3;
                }
            }
#pragma unroll
            for (int s = 0; s < 4; s++) {
                int u = g * 4 + s;
                float bia = s_b2[u];
#pragma unroll
                for (int p = 0; p < 4; p++) {
                    float v = acc2[s][p] + bia;
                    float sig = 1.f / (1.f + expf(-v));
                    int px = pxq * 4 + p;
                    int gy = y0 + (px >> 3), gx = x0 + (px & 7);
                    g_hm[b * KTOT + u * (NY * NX) + gy * NX + gx] = sig;
                }
            }
        } else {
            const float* w0 = s_w2 + 80 * S_W2_STR;
            const float* w1 = s_w2 + 81 * S_W2_STR;
            const float* w2 = s_w2 + 82 * S_W2_STR;
            const float* w3 = s_w2 + 83 * S_W2_STR;
#pragma unroll 4
            for (int ci = 0; ci < 64; ci++) {
                float v0 = w0[ci], v1 = w1[ci], v2 = w2[ci], v3 = w3[ci];
#pragma unroll
                for (int p = 0; p < 4; p++) {
                    float uw = s_u[(pxq * 4 + p) * S_U_STR + 64 + ci];
                    float ur = s_u[(pxq * 4 + p) * S_U_STR + 128 + ci];
                    acc2[0][p] += uw * v0;
                    acc2[1][p] += uw * v1;
                    acc2[2][p] += ur * v2;
                    acc2[3][p] += ur * v3;
                }
            }
            float offx = offsets[b * 3 + 1] * 2.f;
            float offy = offsets[b * 3 + 2] * 2.f;
#pragma unroll
            for (int p = 0; p < 4; p++) {
                int px = pxq * 4 + p;
                int gy = y0 + (px >> 3), gx = x0 + (px & 7);
                float whx = fmaxf(acc2[0][p] + s_b2[80], 0.f);
                float why = fmaxf(acc2[1][p] + s_b2[81], 0.f);
                float rgx = fmaxf(acc2[2][p] + s_b2[82], 0.f);
                float rgy = fmaxf(acc2[3][p] + s_b2[83], 0.f);
                float cx = ((float)gx + offx + rgx) * 4.f;
                float cy = ((float)gy + offy + rgy) * 4.f;
                float* q = g_xywh + ((size_t)b * (NY * NX) + gy * NX + gx) * 4;
                q[0] = cx; q[1] = cy; q[2] = whx * 4.f; q[3] = why * 4.f;
            }
        }
    }
}

/* ---------------- maxima mask + per-block counts ---------------- */
__global__ void mask_kernel() {
    int bid = blockIdx.x;
    int b = bid / 500;
    int i = (bid - b * 500) * 1024 + threadIdx.x;
    const float* hmp = g_hm + (size_t)b * KTOT;
    float c = hmp[i];
    int ch = i / (NY * NX);
    int rem = i - ch * (NY * NX);
    int y = rem / NX;
    int x = rem - y * NX;
    bool f = true;
#pragma unroll
    for (int dy = -1; dy <= 1; dy++)
#pragma unroll
        for (int dx = -1; dx <= 1; dx++) {
            if (dy == 0 && dx == 0) continue;
            int yy = y + dy, xx = x + dx;
            if ((unsigned)yy < NY && (unsigned)xx < NX)
                f = f && (c >= hmp[ch * (NY * NX) + yy * NX + xx]);
        }
    g_flags[(size_t)b * KTOT + i] = f ? 1 : 0;
    unsigned bal = __ballot_sync(0xffffffffu, f);
    __shared__ int wc[32];
    int lane = threadIdx.x & 31, w = threadIdx.x >> 5;
    if (lane == 0) wc[w] = __popc(bal);
    __syncthreads();
    if (threadIdx.x == 0) {
        int s = 0;
        for (int k = 0; k < 32; k++) s += wc[k];
        g_bcount[bid] = s;
    }
}

/* ---------------- per-batch exclusive scan of 500 block counts ---------------- */
__global__ void scan_kernel() {
    __shared__ int s[512];
    int tid = threadIdx.x;
    for (int seg = 0; seg < 2; seg++) {
        int v = (tid < 500) ? g_bcount[seg * 500 + tid] : 0;
        s[tid] = v;
        __syncthreads();
        for (int off = 1; off < 512; off <<= 1) {
            int t = (tid >= off) ? s[tid - off] : 0;
            __syncthreads();
            s[tid] += t;
            __syncthreads();
        }
        if (tid < 500) g_boff[seg * 500 + tid] = s[tid] - v;
        if (tid == 499) g_total[seg] = s[499];
        __syncthreads();
    }
}

/* ---------------- compact peak rows into dense table ---------------- */
__global__ void compact_kernel() {
    int bid = blockIdx.x;
    int b = bid / 500;
    int i = (bid - b * 500) * 1024 + threadIdx.x;
    int f = g_flags[(size_t)b * KTOT + i];
    unsigned bal = __ballot_sync(0xffffffffu, f != 0);
    int lane = threadIdx.x & 31, w = threadIdx.x >> 5;
    __shared__ int wc[32], we[32];
    if (lane == 0) wc[w] = __popc(bal);
    __syncthreads();
    if (w == 0) {
        int v = wc[lane];
        int inc = v;
#pragma unroll
        for (int off = 1; off < 32; off <<= 1) {
            int t = __shfl_up_sync(0xffffffffu, inc, off);
            if (lane >= off) inc += t;
        }
        we[lane] = inc - v;
    }
    __syncthreads();
    if (f) {
        int rank = g_boff[bid] + we[w] + __popc(bal & ((1u << lane) - 1u));
        int ch = i / (NY * NX);
        int rem = i - ch * (NY * NX);
        int y = rem / NX;
        int x = rem - y * NX;
        const float* q = g_xywh + ((size_t)b * (NY * NX) + y * NX + x) * 4;
        float* rd = g_rows + ((size_t)b * KTOT + rank) * 8;
        float4 lo = make_float4(q[0], q[1], q[2], q[3]);
        float4 hi = make_float4(g_hm[(size_t)b * KTOT + i], (float)ch, 0.f, 0.f);
        *(float4*)(rd)     = lo;
        *(float4*)(rd + 4) = hi;
    }
}

/* ---------------- fill: write entire output exactly once ---------------- */
#define TOTAL4 (NBATCH * ELEMS_PER_BATCH / 4)   /* 21,760,000 */

__global__ __launch_bounds__(256) void fill_kernel(float4* __restrict__ out4) {
    int base = blockIdx.x * 1024 + threadIdx.x;
#pragma unroll
    for (int k = 0; k < 4; k++) {
        int q = base + k * 256;
        if (q >= TOTAL4) continue;
        int f0 = q * 4;
        int b = (f0 >= ELEMS_PER_BATCH) ? 1 : 0;
        int e = f0 - b * ELEMS_PER_BATCH;
        int r0 = e / NO;
        int c0 = e - r0 * NO;
        int cnt = g_total[b];
        if (r0 >= cnt) {
            out4[q] = make_float4(0.f, 0.f, 0.f, 0.f);
        } else {
            float v[4];
#pragma unroll
            for (int j = 0; j < 4; j++) {
                int c = c0 + j;
                int r = r0;
                if (c >= NO) { c -= NO; r++; }
                float val = 0.f;
                if (r < cnt) {
                    const float* rd = g_rows + ((size_t)b * KTOT + r) * 8;
                    if (c < 5) val = __ldg(rd + c);
                    else {
                        int ch = (int)__ldg(rd + 5);
                        val = (c == 5 + ch) ? 1.0f : 0.f;
                    }
                }
                v[j] = val;
            }
            out4[q] = make_float4(v[0], v[1], v[2], v[3]);
        }
    }
}

/* ---------------- launcher ---------------- */
extern "C" void kernel_launch(void* const* d_in, const int* in_sizes, int n_in,
                              void* d_out, int out_size) {
    const float* x       = (const float*)d_in[0];
    const float* offsets = (const float*)d_in[1];
    const float* hm_w1   = (const float*)d_in[2];
    const float* hm_b1   = (const float*)d_in[3];
    const float* hm_w2   = (const float*)d_in[4];
    const float* hm_b2   = (const float*)d_in[5];
    const float* wh_w1   = (const float*)d_in[6];
    const float* wh_b1   = (const float*)d_in[7];
    const float* wh_w2   = (const float*)d_in[8];
    const float* wh_b2   = (const float*)d_in[9];
    const float* reg_w1  = (const float*)d_in[10];
    const float* reg_b1  = (const float*)d_in[11];
    const float* reg_w2  = (const float*)d_in[12];
    const float* reg_b2  = (const float*)d_in[13];

    prep_w1<<<(64 * OC3 * 9 + 255) / 256, 256>>>(hm_w1, wh_w1, reg_w1);
    prep_rest<<<(NU * 64 + 255) / 256, 256>>>(hm_b1, wh_b1, reg_b1,
                                              hm_w2, wh_w2, reg_w2,
                                              hm_b2, wh_b2, reg_b2);

    cudaFuncSetAttribute(conv_kernel, cudaFuncAttributeMaxDynamicSharedMemorySize, SMEM_BYTES);
    conv_kernel<<<400, 256, SMEM_BYTES>>>(x, offsets);

    mask_kernel<<<1000, 1024>>>();
    scan_kernel<<<1, 512>>>();
    compact_kernel<<<1000, 1024>>>();

    fill_kernel<<<(TOTAL4 + 1023) / 1024, 256>>>((float4*)d_out);
}